// round 2
// baseline (speedup 1.0000x reference)
#include <cuda_runtime.h>
#include <cuda_bf16.h>

// GCNet cost-volume + softargmax, algebraically collapsed.
//
// Reference semantics:
//   dmin = min_disp/2, dmax = max_disp/2, D = dmax-dmin
//   cost[:, 0:C,  d, h, w] = feaL[c,h,w]                  (constant in d)
//   cost[:, C:2C, d, h, w] = (0 <= w-d < W) ? feaR[c,h,w-d] : 0
//   out = sum_d d * softmax_d(cost)
//
// Left channels: softmax of a constant is uniform -> out = (dmin+dmax-1)/2.
// Right channels: with no max-subtraction (inputs ~N(0,1), exp is safe in f32),
//   each row's exp() is computed once; per-output window sums become inclusive
//   prefix-sum differences:
//     P[x] = prefix exp(feaR[x]),  Q[x] = prefix x*exp(feaR[x])
//     valid x in [lo, hi], hi = w-dmin, lo = max(0, w-dmax+1)
//     S_v = P[hi]-P[lo-1];  T_v = w*S_v - (Q[hi]-Q[lo-1])
//   invalid d (d > w) contribute exp(0)=1 each:
//     z = #invalid,  T_z = sum of those d (arithmetic series)
//     disp = (T_v + T_z) / (S_v + z)

#define BW 256   // W, one thread per column
#define HH 128
#define CC 32

__global__ __launch_bounds__(BW)
void gcnet_softargmax_kernel(const float* __restrict__ feaR,
                             const int* __restrict__ pmin,
                             const int* __restrict__ pmax,
                             float* __restrict__ out)
{
    __shared__ float P[BW];
    __shared__ float Q[BW];

    const int row = blockIdx.x;          // 0 .. C*H-1
    const int c   = row >> 7;            // row / 128
    const int h   = row & 127;           // row % 128
    const int w   = threadIdx.x;

    const int dmin = pmin[0] / 2;        // non-negative: trunc == floor
    const int dmax = pmax[0] / 2;

    // Load one row of feaR, exponentiate once per element.
    const float* rrow = feaR + ((size_t)c * HH + h) * BW;
    float e = __expf(rrow[w]);
    P[w] = e;
    Q[w] = e * (float)w;
    __syncthreads();

    // Hillis-Steele inclusive scan over W=256 (8 steps, double-sync).
    #pragma unroll
    for (int off = 1; off < BW; off <<= 1) {
        float pe = 0.0f, pq = 0.0f;
        if (w >= off) { pe = P[w - off]; pq = Q[w - off]; }
        __syncthreads();
        if (w >= off) { P[w] += pe; Q[w] += pq; }
        __syncthreads();
    }

    // Window sums via prefix differences.
    const int hi = w - dmin;             // last valid source column (may be <0)
    float Sv = 0.0f, Tv = 0.0f;
    if (hi >= 0) {
        int lo = w - dmax + 1;
        if (lo < 0) lo = 0;
        const float Plo = (lo > 0) ? P[lo - 1] : 0.0f;
        const float Qlo = (lo > 0) ? Q[lo - 1] : 0.0f;
        Sv = P[hi] - Plo;
        Tv = (float)w * Sv - (Q[hi] - Qlo);
    }

    // Invalid disparities: d in [max(dmin, w+1), dmax), each contributes exp(0)=1.
    int a = (w + 1 > dmin) ? (w + 1) : dmin;
    int z = dmax - a;
    if (z < 0) z = 0;
    const float Tz = (z > 0) ? 0.5f * (float)(a + dmax - 1) * (float)z : 0.0f;

    const float disp = (Tv + Tz) / (Sv + (float)z);

    const size_t plane = (size_t)HH * BW;
    const size_t base  = (size_t)h * BW + w;
    out[((size_t)(CC + c)) * plane + base] = disp;                       // right channels
    out[((size_t)c) * plane + base] = 0.5f * (float)(dmin + dmax - 1);   // left: uniform softargmax
}

extern "C" void kernel_launch(void* const* d_in, const int* in_sizes, int n_in,
                              void* d_out, int out_size)
{
    // d_in[0] = feaL (unused — left channels are analytically constant)
    const float* feaR = (const float*)d_in[1];
    const int*   pmin = (const int*)d_in[2];
    const int*   pmax = (const int*)d_in[3];
    float*       out  = (float*)d_out;

    gcnet_softargmax_kernel<<<CC * HH, BW>>>(feaR, pmin, pmax, out);
}

// round 3
// speedup vs baseline: 1.4579x; 1.4579x over previous
#include <cuda_runtime.h>
#include <cuda_bf16.h>

// GCNet cost-volume + softargmax, algebraically collapsed.
//
//   dmin = min_disp/2, dmax = max_disp/2
//   Left channels (0..C-1): softmax over d of a d-constant => uniform
//     => out = (dmin+dmax-1)/2 everywhere. feaL never read.
//   Right channels (C..2C-1): per-row prefix sums of exp(feaR):
//     P[x] = prefix exp(feaR[x]),  Q[x] = prefix x*exp(feaR[x])
//     valid src cols x in [lo, hi], hi = w-dmin, lo = max(0, w-dmax+1)
//     S_v = P[hi]-P[lo-1];  T_v = w*S_v - (Q[hi]-Q[lo-1])
//     invalid d contribute exp(0)=1: z of them, T_z arithmetic series
//     disp = (T_v + T_z) / (S_v + z)
//
// R2 profile: Hillis-Steele scan made the kernel shared/issue bound
// (L1 56%, issue 58%, 16 barriers). This version scans in registers via
// warp shuffles: 2 barriers, ~6 shared ops per thread total.

#define BW 256   // W, one thread per column
#define HH 128
#define CC 32

__global__ __launch_bounds__(BW)
void gcnet_softargmax_kernel(const float* __restrict__ feaR,
                             const int* __restrict__ pmin,
                             const int* __restrict__ pmax,
                             float* __restrict__ out)
{
    __shared__ float P[BW];
    __shared__ float Q[BW];
    __shared__ float wP[BW / 32];
    __shared__ float wQ[BW / 32];

    const int row  = blockIdx.x;         // 0 .. C*H-1
    const int c    = row >> 7;           // row / 128
    const int h    = row & 127;          // row % 128
    const int w    = threadIdx.x;
    const int lane = w & 31;
    const int wid  = w >> 5;

    const int dmin = pmin[0] / 2;        // non-negative: trunc == floor
    const int dmax = pmax[0] / 2;

    // Load one row of feaR, exponentiate once per element.
    const float* rrow = feaR + ((size_t)c * HH + h) * BW;
    float e = __expf(rrow[w]);
    float q = e * (float)w;

    // Warp-level inclusive scan of (e, q) in registers (no smem, no barriers).
    #pragma unroll
    for (int off = 1; off < 32; off <<= 1) {
        float pe = __shfl_up_sync(0xFFFFFFFFu, e, off);
        float pq = __shfl_up_sync(0xFFFFFFFFu, q, off);
        if (lane >= off) { e += pe; q += pq; }
    }

    // Publish per-warp totals.
    if (lane == 31) { wP[wid] = e; wQ[wid] = q; }
    __syncthreads();

    // Each thread adds the prefix of preceding warp totals (broadcast LDS).
    float oe = 0.0f, oq = 0.0f;
    #pragma unroll
    for (int k = 0; k < (BW / 32) - 1; k++) {
        if (k < wid) { oe += wP[k]; oq += wQ[k]; }
    }

    // Publish final inclusive prefixes for random-access window lookups.
    P[w] = e + oe;
    Q[w] = q + oq;
    __syncthreads();

    // Window sums via prefix differences.
    const int hi = w - dmin;             // last valid source column (may be <0)
    float Sv = 0.0f, Tv = 0.0f;
    if (hi >= 0) {
        int lo = w - dmax + 1;
        if (lo < 0) lo = 0;
        const float Plo = (lo > 0) ? P[lo - 1] : 0.0f;
        const float Qlo = (lo > 0) ? Q[lo - 1] : 0.0f;
        Sv = P[hi] - Plo;
        Tv = (float)w * Sv - (Q[hi] - Qlo);
    }

    // Invalid disparities: d in [max(dmin, w+1), dmax), each contributes exp(0)=1.
    int a = (w + 1 > dmin) ? (w + 1) : dmin;
    int z = dmax - a;
    if (z < 0) z = 0;
    const float Tz = (z > 0) ? 0.5f * (float)(a + dmax - 1) * (float)z : 0.0f;

    const float disp = (Tv + Tz) / (Sv + (float)z);

    const size_t plane = (size_t)HH * BW;
    const size_t base  = (size_t)h * BW + w;
    out[((size_t)(CC + c)) * plane + base] = disp;                       // right channels
    out[((size_t)c) * plane + base] = 0.5f * (float)(dmin + dmax - 1);   // left: uniform softargmax
}

extern "C" void kernel_launch(void* const* d_in, const int* in_sizes, int n_in,
                              void* d_out, int out_size)
{
    // d_in[0] = feaL (unused — left channels are analytically constant)
    const float* feaR = (const float*)d_in[1];
    const int*   pmin = (const int*)d_in[2];
    const int*   pmax = (const int*)d_in[3];
    float*       out  = (float*)d_out;

    gcnet_softargmax_kernel<<<CC * HH, BW>>>(feaR, pmin, pmax, out);
}

// round 4
// speedup vs baseline: 1.7018x; 1.1673x over previous
#include <cuda_runtime.h>
#include <cuda_bf16.h>

// GCNet cost-volume + softargmax, algebraically collapsed.
//
//   dmin = min_disp/2, dmax = max_disp/2
//   Left channels: softmax of d-constant => uniform => out = (dmin+dmax-1)/2.
//   Right channels: per-row prefix sums of exp(feaR):
//     P[x] = prefix exp(feaR[x]), Q[x] = prefix x*exp(feaR[x])
//     valid src x in [lo, hi], hi = w-dmin, lo = max(0, w-dmax+1)
//     Sv = P[hi]-P[lo-1];  Tv = w*Sv - (Q[hi]-Q[lo-1])
//     invalid d contribute exp(0)=1: z of them, Tz arithmetic series
//     disp = (Tv+Tz)/(Sv+z)
//
// R3 finding: real bottleneck is the MUFU pipe (1.05M EX2 @ 74/cyc = 7.2us
// floor), not issue. This version: (a) 3:1 MUFU/polynomial exp split to run
// the MUFU and FMA pipes in parallel, (b) x4 thread coarsening (serial scan
// of 4 + warp scan of totals) to cut SHFL/indexing overhead and use 128-bit
// memory ops throughout.

#define BW  256   // W
#define HH  128
#define CC  32
#define RPB 4     // rows per block
#define TPR 64    // threads per row (2 warps)

// exp(x) via 2^(x*log2e), FMA pipe only. |x| << 2^22 assumed (inputs ~N(0,1)).
// Range reduce with the 1.5*2^23 magic constant (round-to-nearest-even),
// 2^f for f in [-0.5,0.5] via degree-4 Taylor of e^(f*ln2), scale by 2^n
// through exponent-field integer add. Abs rel err ~4e-5.
__device__ __forceinline__ float fast_exp(float x)
{
    float y  = x * 1.4426950408889634f;
    float fn = y + 12582912.0f;                      // round(y) encoded
    int   ei = __float_as_int(fn) - 0x4B400000;      // integer n
    float n  = fn - 12582912.0f;
    float f  = y - n;                                // [-0.5, 0.5]
    float t  = f * 0.6931471805599453f;
    float p  = 0.041666668f;
    p = fmaf(p, t, 0.16666667f);
    p = fmaf(p, t, 0.5f);
    p = fmaf(p, t, 1.0f);
    p = fmaf(p, t, 1.0f);
    return __int_as_float(__float_as_int(p) + (ei << 23));
}

__global__ __launch_bounds__(RPB * TPR)
void gcnet_softargmax_kernel(const float* __restrict__ feaR,
                             const int* __restrict__ pmin,
                             const int* __restrict__ pmax,
                             float* __restrict__ out)
{
    __shared__ __align__(16) float P[RPB][BW];
    __shared__ __align__(16) float Q[RPB][BW];
    __shared__ float wTe[RPB];
    __shared__ float wTq[RPB];

    const int tid  = threadIdx.x;
    const int rloc = tid >> 6;           // row within block (warp-aligned: TPR=64)
    const int t    = tid & 63;           // thread within row
    const int lane = tid & 31;
    const int wir  = (tid >> 5) & 1;     // warp index within row
    const int row  = blockIdx.x * RPB + rloc;   // 0..4095 == c*H+h
    const int w0   = t << 2;             // first of 4 columns

    const int dmin = pmin[0] / 2;        // non-negative: trunc == floor
    const int dmax = pmax[0] / 2;

    // 128-bit load of this thread's 4 columns.
    const float4 v = *reinterpret_cast<const float4*>(feaR + ((size_t)row << 8) + w0);

    // 3 exps on MUFU, 1 on FMA pipe (pipe-parallel).
    const float e0 = __expf(v.x);
    const float e1 = __expf(v.y);
    const float e2 = __expf(v.z);
    const float e3 = fast_exp(v.w);

    // Thread-local inclusive sums over the 4 elements.
    const float ce0 = e0;
    const float ce1 = ce0 + e1;
    const float ce2 = ce1 + e2;
    const float ce3 = ce2 + e3;
    const float cq0 = e0 * (float)w0;
    const float cq1 = fmaf(e1, (float)(w0 + 1), cq0);
    const float cq2 = fmaf(e2, (float)(w0 + 2), cq1);
    const float cq3 = fmaf(e3, (float)(w0 + 3), cq2);

    // Warp-level inclusive scan of per-thread totals.
    float ie = ce3, iq = cq3;
    #pragma unroll
    for (int off = 1; off < 32; off <<= 1) {
        float a = __shfl_up_sync(0xFFFFFFFFu, ie, off);
        float b = __shfl_up_sync(0xFFFFFFFFu, iq, off);
        if (lane >= off) { ie += a; iq += b; }
    }
    float offe = ie - ce3;               // exclusive prefix (exact 0 for lane 0)
    float offq = iq - cq3;

    // Cross-warp (2 warps per row): warp 1 adds warp 0's total.
    if (lane == 31 && wir == 0) { wTe[rloc] = ie; wTq[rloc] = iq; }
    __syncthreads();
    if (wir == 1) { offe += wTe[rloc]; offq += wTq[rloc]; }

    // Publish inclusive prefixes (one 128-bit STS each).
    *reinterpret_cast<float4*>(&P[rloc][w0]) =
        make_float4(offe + ce0, offe + ce1, offe + ce2, offe + ce3);
    *reinterpret_cast<float4*>(&Q[rloc][w0]) =
        make_float4(offq + cq0, offq + cq1, offq + cq2, offq + cq3);
    __syncthreads();

    // Window sums via prefix differences, 4 outputs per thread.
    float res[4];
    #pragma unroll
    for (int k = 0; k < 4; k++) {
        const int w  = w0 + k;
        const int hi = w - dmin;
        float Sv = 0.0f, Tv = 0.0f;
        if (hi >= 0) {
            int lo = w - dmax + 1;
            if (lo < 0) lo = 0;
            const float Plo = (lo > 0) ? P[rloc][lo - 1] : 0.0f;
            const float Qlo = (lo > 0) ? Q[rloc][lo - 1] : 0.0f;
            Sv = P[rloc][hi] - Plo;
            Tv = (float)w * Sv - (Q[rloc][hi] - Qlo);
        }
        int a = (w + 1 > dmin) ? (w + 1) : dmin;
        int z = dmax - a;
        if (z < 0) z = 0;
        const float Tz = (z > 0) ? 0.5f * (float)(a + dmax - 1) * (float)z : 0.0f;
        res[k] = (Tv + Tz) / (Sv + (float)z);
    }

    const int c = row >> 7;
    const int h = row & 127;
    const size_t plane = (size_t)HH * BW;
    const size_t base  = (size_t)h * BW + w0;
    const float  lc    = 0.5f * (float)(dmin + dmax - 1);

    *reinterpret_cast<float4*>(out + ((size_t)(CC + c)) * plane + base) =
        make_float4(res[0], res[1], res[2], res[3]);
    *reinterpret_cast<float4*>(out + ((size_t)c) * plane + base) =
        make_float4(lc, lc, lc, lc);
}

extern "C" void kernel_launch(void* const* d_in, const int* in_sizes, int n_in,
                              void* d_out, int out_size)
{
    // d_in[0] = feaL (unused — left channels are analytically constant)
    const float* feaR = (const float*)d_in[1];
    const int*   pmin = (const int*)d_in[2];
    const int*   pmax = (const int*)d_in[3];
    float*       out  = (float*)d_out;

    gcnet_softargmax_kernel<<<(CC * HH) / RPB, RPB * TPR>>>(feaR, pmin, pmax, out);
}

// round 5
// speedup vs baseline: 1.8281x; 1.0742x over previous
#include <cuda_runtime.h>
#include <cuda_bf16.h>

// GCNet cost-volume + softargmax, algebraically collapsed.
//
//   dmin = min_disp/2, dmax = max_disp/2
//   Left channels: softmax of d-constant => uniform => out = (dmin+dmax-1)/2.
//   Right channels: per-row prefix sums of exp(feaR):
//     P[x] = prefix exp(feaR[x]), Q[x] = prefix x*exp(feaR[x])
//     valid src x in [lo, hi], hi = w-dmin, lo = max(0, w-dmax+1)
//     Sv = P[hi]-P[lo-1];  Tv = w*Sv - (Q[hi]-Q[lo-1])
//     invalid d contribute exp(0)=1: z of them, Tz arithmetic series
//     disp = (Tv+Tz)/(Sv+z)
//
// R4 finding: no pipe saturated -> latency/overhead bound (barriers, LDS
// round-trips, shfl chains, instruction count). This version:
//   * one warp per row, 8 cols/thread: no cross-warp scan, no __syncthreads
//   * specialized path for (dmin==0, dmax==64): P[hi] is the thread's own
//     prefix register and P[lo-1] is exactly shfl_up(Pk, 8) -> the whole
//     window phase runs in registers, zero smem, zero barriers
//   * generic smem fallback (warp-private rows, __syncwarp only)
//   * 4 MUFU : 4 FMA-poly exp split, __fdividef epilogue

#define BW  256   // W
#define HH  128
#define CC  32
#define RPB 8     // rows (=warps) per block
#define NTH (RPB * 32)

// exp(x) on the FMA pipe only: 2^(x*log2e) with magic-number round-to-nearest
// range reduction and degree-4 Taylor in f (coeffs pre-scaled by ln2 powers).
// Valid for |x| < ~80 (inputs ~N(0,1)); rel err ~4e-5.
__device__ __forceinline__ float fast_exp(float x)
{
    const float L2E   = 1.4426950408889634f;
    const float MAGIC = 12582912.0f;                 // 1.5 * 2^23
    float fn = fmaf(x, L2E, MAGIC);
    int   ei = __float_as_int(fn) - 0x4B400000;      // integer n
    float n  = fn - MAGIC;
    float f  = fmaf(x, L2E, -n);                     // [-0.5, 0.5]
    float p  = 0.0096180f;                           // ln2^4/24
    p = fmaf(p, f, 0.0555041f);                      // ln2^3/6
    p = fmaf(p, f, 0.2402265f);                      // ln2^2/2
    p = fmaf(p, f, 0.6931472f);                      // ln2
    p = fmaf(p, f, 1.0f);
    return __int_as_float(__float_as_int(p) + (ei << 23));
}

__global__ __launch_bounds__(NTH)
void gcnet_softargmax_kernel(const float* __restrict__ feaR,
                             const int* __restrict__ pmin,
                             const int* __restrict__ pmax,
                             float* __restrict__ out)
{
    __shared__ float sP[RPB][BW];   // generic fallback only
    __shared__ float sQ[RPB][BW];

    const int tid  = threadIdx.x;
    const int rloc = tid >> 5;               // warp = row within block
    const int lane = tid & 31;
    const int row  = blockIdx.x * RPB + rloc;  // 0..4095 == c*H + h
    const int w0   = lane << 3;              // first of 8 columns

    const int dmin = pmin[0] / 2;            // non-negative: trunc == floor
    const int dmax = pmax[0] / 2;

    // 2x 128-bit loads: this thread's 8 columns.
    const float4 va = *reinterpret_cast<const float4*>(feaR + ((size_t)row << 8) + w0);
    const float4 vb = *reinterpret_cast<const float4*>(feaR + ((size_t)row << 8) + w0 + 4);

    // 4 exps on MUFU, 4 on the FMA pipe.
    float e0 = __expf(va.x);
    float e1 = fast_exp(va.y);
    float e2 = __expf(va.z);
    float e3 = fast_exp(va.w);
    float e4 = __expf(vb.x);
    float e5 = fast_exp(vb.y);
    float e6 = __expf(vb.z);
    float e7 = fast_exp(vb.w);

    // Thread-local inclusive prefixes over 8 elements.
    float ce[8], cq[8];
    ce[0] = e0;                         cq[0] = e0 * (float)w0;
    ce[1] = ce[0] + e1;                 cq[1] = fmaf(e1, (float)(w0 + 1), cq[0]);
    ce[2] = ce[1] + e2;                 cq[2] = fmaf(e2, (float)(w0 + 2), cq[1]);
    ce[3] = ce[2] + e3;                 cq[3] = fmaf(e3, (float)(w0 + 3), cq[2]);
    ce[4] = ce[3] + e4;                 cq[4] = fmaf(e4, (float)(w0 + 4), cq[3]);
    ce[5] = ce[4] + e5;                 cq[5] = fmaf(e5, (float)(w0 + 5), cq[4]);
    ce[6] = ce[5] + e6;                 cq[6] = fmaf(e6, (float)(w0 + 6), cq[5]);
    ce[7] = ce[6] + e7;                 cq[7] = fmaf(e7, (float)(w0 + 7), cq[6]);

    // Warp inclusive scan of per-thread totals (5 double-shfl steps).
    float ie = ce[7], iq = cq[7];
    #pragma unroll
    for (int off = 1; off < 32; off <<= 1) {
        float a = __shfl_up_sync(0xFFFFFFFFu, ie, off);
        float b = __shfl_up_sync(0xFFFFFFFFu, iq, off);
        if (lane >= off) { ie += a; iq += b; }
    }
    const float offe = ie - ce[7];      // exclusive prefix (exact 0 for lane 0)
    const float offq = iq - cq[7];

    // Full row-inclusive prefixes, in registers.
    float P[8], Q[8];
    #pragma unroll
    for (int k = 0; k < 8; k++) { P[k] = offe + ce[k]; Q[k] = offq + cq[k]; }

    float res[8];

    if (dmin == 0 && dmax == 64) {
        // ---- Specialized all-register path (the shapes this problem runs) ----
        // hi = w  -> own register.  lo-1 = w-64 -> shfl_up by 8 lanes, same k.
        #pragma unroll
        for (int k = 0; k < 8; k++) {
            const int   w   = w0 + k;
            const float Pm  = __shfl_up_sync(0xFFFFFFFFu, P[k], 8);
            const float Qm  = __shfl_up_sync(0xFFFFFFFFu, Q[k], 8);
            const float Plo = (lane >= 8) ? Pm : 0.0f;
            const float Qlo = (lane >= 8) ? Qm : 0.0f;
            const float Sv  = P[k] - Plo;
            const float Tv  = fmaf((float)w, Sv, -(Q[k] - Qlo));
            const int   z   = (w < 63) ? (63 - w) : 0;
            const float Tz  = (z > 0) ? 0.5f * (float)(w + 64) * (float)z : 0.0f;
            res[k] = __fdividef(Tv + Tz, Sv + (float)z);
        }
    } else {
        // ---- Generic fallback: publish prefixes to warp-private smem row ----
        #pragma unroll
        for (int k = 0; k < 8; k += 4) {
            *reinterpret_cast<float4*>(&sP[rloc][w0 + k]) =
                make_float4(P[k], P[k + 1], P[k + 2], P[k + 3]);
            *reinterpret_cast<float4*>(&sQ[rloc][w0 + k]) =
                make_float4(Q[k], Q[k + 1], Q[k + 2], Q[k + 3]);
        }
        __syncwarp();
        #pragma unroll
        for (int k = 0; k < 8; k++) {
            const int w  = w0 + k;
            const int hi = w - dmin;
            float Sv = 0.0f, Tv = 0.0f;
            if (hi >= 0) {
                int lo = w - dmax + 1;
                if (lo < 0) lo = 0;
                const float Plo = (lo > 0) ? sP[rloc][lo - 1] : 0.0f;
                const float Qlo = (lo > 0) ? sQ[rloc][lo - 1] : 0.0f;
                Sv = sP[rloc][hi] - Plo;
                Tv = fmaf((float)w, Sv, -(sQ[rloc][hi] - Qlo));
            }
            int a = (w + 1 > dmin) ? (w + 1) : dmin;
            int z = dmax - a;
            if (z < 0) z = 0;
            const float Tz = (z > 0) ? 0.5f * (float)(a + dmax - 1) * (float)z : 0.0f;
            res[k] = __fdividef(Tv + Tz, Sv + (float)z);
        }
    }

    const int c = row >> 7;
    const int h = row & 127;
    const size_t plane = (size_t)HH * BW;
    const size_t base  = (size_t)h * BW + w0;
    const float  lc    = 0.5f * (float)(dmin + dmax - 1);

    float* rp = out + ((size_t)(CC + c)) * plane + base;   // right channels
    float* lp = out + ((size_t)c) * plane + base;          // left channels
    *reinterpret_cast<float4*>(rp)     = make_float4(res[0], res[1], res[2], res[3]);
    *reinterpret_cast<float4*>(rp + 4) = make_float4(res[4], res[5], res[6], res[7]);
    *reinterpret_cast<float4*>(lp)     = make_float4(lc, lc, lc, lc);
    *reinterpret_cast<float4*>(lp + 4) = make_float4(lc, lc, lc, lc);
}

extern "C" void kernel_launch(void* const* d_in, const int* in_sizes, int n_in,
                              void* d_out, int out_size)
{
    // d_in[0] = feaL (unused — left channels are analytically constant)
    const float* feaR = (const float*)d_in[1];
    const int*   pmin = (const int*)d_in[2];
    const int*   pmax = (const int*)d_in[3];
    float*       out  = (float*)d_out;

    gcnet_softargmax_kernel<<<(CC * HH) / RPB, NTH>>>(feaR, pmin, pmax, out);
}

// round 6
// speedup vs baseline: 2.0260x; 1.1082x over previous
#include <cuda_runtime.h>
#include <cuda_bf16.h>

// GCNet cost-volume + softargmax, algebraically collapsed.
//
//   dmin = min_disp/2, dmax = max_disp/2
//   Left channels: softmax of d-constant => uniform => out = (dmin+dmax-1)/2.
//   Right channels: per-row prefix sums of exp(feaR):
//     P[x] = prefix exp(feaR[x]), Q[x] = prefix x*exp(feaR[x])
//     valid src x in [lo, hi], hi = w-dmin, lo = max(0, w-dmax+1)
//     Sv = P[hi]-P[lo-1];  Tv = w*Sv - (Q[hi]-Q[lo-1])
//     invalid d contribute exp(0)=1: z of them, Tz arithmetic series
//     disp = (Tv+Tz)/(Sv+z)
//
// R5 findings: work-limited occupancy (4096 warps = 43% cap), nothing
// saturated, latency/overhead regime. MUFU demand is ~440 cycles chip-wide,
// so the FMA-poly exp split was pure instruction bloat. This version:
//   * all 8 exps on MUFU (-28 instr/thread)
//   * 2-warp blocks, grid 2048: finer scheduling granularity, 7% tail
//     imbalance instead of 16% (hot path has no barriers, block shape free)
//   * epilogue kept in registers: window lookups are shfl_up(.,8)

#define BW  256   // W
#define HH  128
#define CC  32
#define RPB 2     // rows (=warps) per block
#define NTH (RPB * 32)

__global__ __launch_bounds__(NTH)
void gcnet_softargmax_kernel(const float* __restrict__ feaR,
                             const int* __restrict__ pmin,
                             const int* __restrict__ pmax,
                             float* __restrict__ out)
{
    __shared__ float sP[RPB][BW];   // generic fallback only
    __shared__ float sQ[RPB][BW];

    const int tid  = threadIdx.x;
    const int rloc = tid >> 5;               // warp = row within block
    const int lane = tid & 31;
    const int row  = blockIdx.x * RPB + rloc;  // 0..4095 == c*H + h
    const int w0   = lane << 3;              // first of 8 columns

    const int dmin = pmin[0] / 2;            // non-negative: trunc == floor
    const int dmax = pmax[0] / 2;

    // 2x 128-bit loads: this thread's 8 columns.
    const float* rp0 = feaR + ((size_t)row << 8) + w0;
    const float4 va = *reinterpret_cast<const float4*>(rp0);
    const float4 vb = *reinterpret_cast<const float4*>(rp0 + 4);

    // All exps on MUFU (total MUFU demand ~440 cycles chip-wide: never binding).
    const float e0 = __expf(va.x);
    const float e1 = __expf(va.y);
    const float e2 = __expf(va.z);
    const float e3 = __expf(va.w);
    const float e4 = __expf(vb.x);
    const float e5 = __expf(vb.y);
    const float e6 = __expf(vb.z);
    const float e7 = __expf(vb.w);

    // Thread-local inclusive prefixes over 8 elements.
    float ce[8], cq[8];
    ce[0] = e0;             cq[0] = e0 * (float)w0;
    ce[1] = ce[0] + e1;     cq[1] = fmaf(e1, (float)(w0 + 1), cq[0]);
    ce[2] = ce[1] + e2;     cq[2] = fmaf(e2, (float)(w0 + 2), cq[1]);
    ce[3] = ce[2] + e3;     cq[3] = fmaf(e3, (float)(w0 + 3), cq[2]);
    ce[4] = ce[3] + e4;     cq[4] = fmaf(e4, (float)(w0 + 4), cq[3]);
    ce[5] = ce[4] + e5;     cq[5] = fmaf(e5, (float)(w0 + 5), cq[4]);
    ce[6] = ce[5] + e6;     cq[6] = fmaf(e6, (float)(w0 + 6), cq[5]);
    ce[7] = ce[6] + e7;     cq[7] = fmaf(e7, (float)(w0 + 7), cq[6]);

    // Warp inclusive scan of per-thread totals (5 double-shfl steps).
    float ie = ce[7], iq = cq[7];
    #pragma unroll
    for (int off = 1; off < 32; off <<= 1) {
        float a = __shfl_up_sync(0xFFFFFFFFu, ie, off);
        float b = __shfl_up_sync(0xFFFFFFFFu, iq, off);
        if (lane >= off) { ie += a; iq += b; }
    }
    const float offe = ie - ce[7];      // exclusive prefix (exact 0 for lane 0)
    const float offq = iq - cq[7];

    // Full row-inclusive prefixes, in registers.
    float P[8], Q[8];
    #pragma unroll
    for (int k = 0; k < 8; k++) { P[k] = offe + ce[k]; Q[k] = offq + cq[k]; }

    float res[8];

    if (dmin == 0 && dmax == 64) {
        // ---- Specialized all-register path (the shapes this problem runs) ----
        // hi = w -> own register.  lo-1 = w-64 -> shfl_up by 8 lanes, same k.
        #pragma unroll
        for (int k = 0; k < 8; k++) {
            const int   w   = w0 + k;
            const float Pm  = __shfl_up_sync(0xFFFFFFFFu, P[k], 8);
            const float Qm  = __shfl_up_sync(0xFFFFFFFFu, Q[k], 8);
            const float Plo = (lane >= 8) ? Pm : 0.0f;
            const float Qlo = (lane >= 8) ? Qm : 0.0f;
            const float Sv  = P[k] - Plo;
            const float Tv  = fmaf((float)w, Sv, -(Q[k] - Qlo));
            // invalid d: d in [w+1, 64) -> z = max(63-w, 0), Tz = (w+64)z/2
            const float zf  = (w < 63) ? (float)(63 - w) : 0.0f;
            const float Tz  = 0.5f * (float)(w + 64) * zf;
            res[k] = __fdividef(Tv + Tz, Sv + zf);
        }
    } else {
        // ---- Generic fallback: publish prefixes to warp-private smem row ----
        #pragma unroll
        for (int k = 0; k < 8; k += 4) {
            *reinterpret_cast<float4*>(&sP[rloc][w0 + k]) =
                make_float4(P[k], P[k + 1], P[k + 2], P[k + 3]);
            *reinterpret_cast<float4*>(&sQ[rloc][w0 + k]) =
                make_float4(Q[k], Q[k + 1], Q[k + 2], Q[k + 3]);
        }
        __syncwarp();
        #pragma unroll
        for (int k = 0; k < 8; k++) {
            const int w  = w0 + k;
            const int hi = w - dmin;
            float Sv = 0.0f, Tv = 0.0f;
            if (hi >= 0) {
                int lo = w - dmax + 1;
                if (lo < 0) lo = 0;
                const float Plo = (lo > 0) ? sP[rloc][lo - 1] : 0.0f;
                const float Qlo = (lo > 0) ? sQ[rloc][lo - 1] : 0.0f;
                Sv = sP[rloc][hi] - Plo;
                Tv = fmaf((float)w, Sv, -(sQ[rloc][hi] - Qlo));
            }
            int a = (w + 1 > dmin) ? (w + 1) : dmin;
            int z = dmax - a;
            if (z < 0) z = 0;
            const float Tz = (z > 0) ? 0.5f * (float)(a + dmax - 1) * (float)z : 0.0f;
            res[k] = __fdividef(Tv + Tz, Sv + (float)z);
        }
    }

    const int c = row >> 7;
    const int h = row & 127;
    const size_t plane = (size_t)HH * BW;
    const size_t base  = (size_t)h * BW + w0;
    const float  lc    = 0.5f * (float)(dmin + dmax - 1);

    float* rp = out + ((size_t)(CC + c)) * plane + base;   // right channels
    float* lp = out + ((size_t)c) * plane + base;          // left channels
    *reinterpret_cast<float4*>(rp)     = make_float4(res[0], res[1], res[2], res[3]);
    *reinterpret_cast<float4*>(rp + 4) = make_float4(res[4], res[5], res[6], res[7]);
    *reinterpret_cast<float4*>(lp)     = make_float4(lc, lc, lc, lc);
    *reinterpret_cast<float4*>(lp + 4) = make_float4(lc, lc, lc, lc);
}

extern "C" void kernel_launch(void* const* d_in, const int* in_sizes, int n_in,
                              void* d_out, int out_size)
{
    // d_in[0] = feaL (unused — left channels are analytically constant)
    const float* feaR = (const float*)d_in[1];
    const int*   pmin = (const int*)d_in[2];
    const int*   pmax = (const int*)d_in[3];
    float*       out  = (float*)d_out;

    gcnet_softargmax_kernel<<<(CC * HH) / RPB, NTH>>>(feaR, pmin, pmax, out);
}